// round 7
// baseline (speedup 1.0000x reference)
#include <cuda_runtime.h>
#include <cuda_bf16.h>
#include <cstdint>

// Problem constants (match reference)
#define BATCH      4
#define SEQ_LEN    8192
#define EMBED_DIM  512
#define NBUCKETS   500000
#define HASH_MASK  0x7FFFFFu   // 2^23 - 1
#define HASH_BASE  260u        // VOCAB + 1
#define MAX_N      8

// Precomputed sum of the 6 size_w rows (constant across all positions).
__device__ float g_sizesum[EMBED_DIM];

__global__ __launch_bounds__(128, 1)
void sizesum_kernel(const float* __restrict__ size_w)
{
    const int d4 = threadIdx.x;          // 0..127 float4 lanes
    const float4* z4 = (const float4*)size_w;
    float4 a = z4[d4];
    #pragma unroll
    for (int r = 1; r < MAX_N - 2; ++r) {
        float4 v = z4[r * 128 + d4];
        a.x += v.x; a.y += v.y; a.z += v.z; a.w += v.w;
    }
    ((float4*)g_sizesum)[d4] = a;
}

// One CTA per (b, s) position. 128 threads, each owns one float4 (4 floats)
// of the 512-dim embedding. 12 CTAs/SM: this kernel is occupancy->MLP
// sensitive (R5 showed -13pp occ costs ~3pp DRAM).
__global__ __launch_bounds__(128, 12)
void hash_ngram_kernel(const int* __restrict__ tokens,
                       const float* __restrict__ main_w,
                       const float* __restrict__ shared_w,
                       float* __restrict__ out)
{
    const int pos = blockIdx.x;           // 0 .. BATCH*SEQ_LEN-1
    const int b   = pos >> 13;            // / SEQ_LEN
    const int s   = pos & (SEQ_LEN - 1);  // % SEQ_LEN

    __shared__ int tok[MAX_N];            // t[s], t[s-1], ..., t[s-7]

    if (threadIdx.x < MAX_N) {
        const int j = threadIdx.x;
        tok[j] = (s - j >= 0) ? tokens[b * SEQ_LEN + (s - j)] : 0;
    }
    __syncthreads();

    // Every thread computes the 6 bucket indices redundantly (pure ALU,
    // ~30 int ops) — avoids a second barrier / single-thread serialization.
    int sidx[MAX_N - 2];
    {
        unsigned P   = 1u;   // 260^j mod 2^23
        unsigned acc = 0u;   // running sum of masked terms
        #pragma unroll
        for (int j = 0; j < MAX_N; ++j) {
            acc += ((unsigned)tok[j] * P) & HASH_MASK;   // t[s-j]*260^j mod 2^23
            P = (P * HASH_BASE) & HASH_MASK;
            const int n = j + 1;                          // n-gram length
            if (n >= 3) {
                const unsigned h = acc & HASH_MASK;       // sum mod 2^23
                sidx[n - 3] = (s >= n - 1) ? (int)(h % NBUCKETS) : 0;
            }
        }
    }

    const int d4 = threadIdx.x;  // float4 lane, 0..127 (512/4)
    const float4* __restrict__ g4 = (const float4*)shared_w;
    const float4* __restrict__ m4 = (const float4*)main_w;

    // Issue the 6 DRAM gathers first for maximum MLP, then the cached loads.
    float4 vg[MAX_N - 2];
    #pragma unroll
    for (int r = 0; r < MAX_N - 2; ++r)
        vg[r] = __ldg(&g4[(size_t)sidx[r] * 128 + d4]);

    float4 vm = __ldg(&m4[(size_t)tok[0] * 128 + d4]);            // L2-resident
    float4 vz = ((const float4*)g_sizesum)[d4];                   // L1/L2-resident

    float ax = vm.x + vz.x, ay = vm.y + vz.y, az = vm.z + vz.z, aw = vm.w + vz.w;
    #pragma unroll
    for (int r = 0; r < MAX_N - 2; ++r) {
        ax += vg[r].x;
        ay += vg[r].y;
        az += vg[r].z;
        aw += vg[r].w;
    }

    const float inv = 1.0f / 7.0f;   // 1 + (MAX_N - 2) contributors
    float4 o;
    o.x = ax * inv; o.y = ay * inv; o.z = az * inv; o.w = aw * inv;
    // Streaming store: don't let the 64MB output evict gather lines from L2.
    __stcs(&((float4*)out)[(size_t)pos * 128 + d4], o);
}

extern "C" void kernel_launch(void* const* d_in, const int* in_sizes, int n_in,
                              void* d_out, int out_size)
{
    const int*   tokens   = (const int*)  d_in[0];   // [4, 8192] int32
    const float* main_w   = (const float*)d_in[1];   // [259, 512] f32
    const float* shared_w = (const float*)d_in[2];   // [500000, 512] f32
    const float* size_w   = (const float*)d_in[3];   // [6, 512] f32
    float*       out      = (float*)d_out;           // [4, 8192, 512] f32

    (void)in_sizes; (void)n_in; (void)out_size;

    sizesum_kernel<<<1, 128>>>(size_w);
    hash_ngram_kernel<<<BATCH * SEQ_LEN, 128>>>(tokens, main_w, shared_w, out);
}

// round 8
// speedup vs baseline: 1.0147x; 1.0147x over previous
#include <cuda_runtime.h>
#include <cuda_bf16.h>
#include <cstdint>

// Problem constants (match reference)
#define BATCH      4
#define SEQ_LEN    8192
#define EMBED_DIM  512
#define NBUCKETS   500000
#define HASH_MASK  0x7FFFFFu   // 2^23 - 1
#define HASH_BASE  260u        // VOCAB + 1
#define MAX_N      8

// One CTA per (b, s) position. 128 threads, each owns one float4 of the
// 512-dim embedding. Single launch: the 6 size_w rows (12KB, L1-resident
// after wave 1) are re-summed per thread into the running accumulator —
// this deletes the prologue kernel + graph gap (~1.9us) while keeping
// live state across the in-flight gathers to one float4.
__global__ __launch_bounds__(128, 10)
void hash_ngram_kernel(const int* __restrict__ tokens,
                       const float* __restrict__ main_w,
                       const float* __restrict__ shared_w,
                       const float* __restrict__ size_w,
                       float* __restrict__ out)
{
    const int pos = blockIdx.x;           // 0 .. BATCH*SEQ_LEN-1
    const int b   = pos >> 13;            // / SEQ_LEN
    const int s   = pos & (SEQ_LEN - 1);  // % SEQ_LEN

    __shared__ int tok[MAX_N];            // t[s], t[s-1], ..., t[s-7]

    if (threadIdx.x < MAX_N) {
        const int j = threadIdx.x;
        tok[j] = (s - j >= 0) ? tokens[b * SEQ_LEN + (s - j)] : 0;
    }
    __syncthreads();

    // Every thread computes the 6 bucket indices redundantly (pure ALU,
    // ~30 int ops) — avoids a second barrier / single-thread serialization.
    int sidx[MAX_N - 2];
    {
        unsigned P   = 1u;   // 260^j mod 2^23
        unsigned acc = 0u;   // running sum of masked terms
        #pragma unroll
        for (int j = 0; j < MAX_N; ++j) {
            acc += ((unsigned)tok[j] * P) & HASH_MASK;   // t[s-j]*260^j mod 2^23
            P = (P * HASH_BASE) & HASH_MASK;
            const int n = j + 1;                          // n-gram length
            if (n >= 3) {
                const unsigned h = acc & HASH_MASK;       // sum mod 2^23
                sidx[n - 3] = (s >= n - 1) ? (int)(h % NBUCKETS) : 0;
            }
        }
    }

    const int d4 = threadIdx.x;  // float4 lane, 0..127 (512/4)
    const float4* __restrict__ g4 = (const float4*)shared_w;
    const float4* __restrict__ m4 = (const float4*)main_w;
    const float4* __restrict__ z4 = (const float4*)size_w;

    // Issue the 6 DRAM gathers first for maximum MLP.
    float4 vg[MAX_N - 2];
    #pragma unroll
    for (int r = 0; r < MAX_N - 2; ++r)
        vg[r] = __ldg(&g4[(size_t)sidx[r] * 128 + d4]);

    // While gathers are in flight: cached contributions, accumulated
    // immediately (single float4 of live state, no arrays).
    float4 vm = __ldg(&m4[(size_t)tok[0] * 128 + d4]);   // L2-resident
    float ax = vm.x, ay = vm.y, az = vm.z, aw = vm.w;
    #pragma unroll
    for (int r = 0; r < MAX_N - 2; ++r) {
        const float4 vz = __ldg(&z4[(size_t)r * 128 + d4]);  // L1-resident
        ax += vz.x; ay += vz.y; az += vz.z; aw += vz.w;
    }

    // Consume the gathers.
    #pragma unroll
    for (int r = 0; r < MAX_N - 2; ++r) {
        ax += vg[r].x;
        ay += vg[r].y;
        az += vg[r].z;
        aw += vg[r].w;
    }

    const float inv = 1.0f / 7.0f;   // 1 + (MAX_N - 2) contributors
    float4 o;
    o.x = ax * inv; o.y = ay * inv; o.z = az * inv; o.w = aw * inv;
    // Streaming store: don't let the 64MB output evict gather lines from L2.
    __stcs(&((float4*)out)[(size_t)pos * 128 + d4], o);
}

extern "C" void kernel_launch(void* const* d_in, const int* in_sizes, int n_in,
                              void* d_out, int out_size)
{
    const int*   tokens   = (const int*)  d_in[0];   // [4, 8192] int32
    const float* main_w   = (const float*)d_in[1];   // [259, 512] f32
    const float* shared_w = (const float*)d_in[2];   // [500000, 512] f32
    const float* size_w   = (const float*)d_in[3];   // [6, 512] f32
    float*       out      = (float*)d_out;           // [4, 8192, 512] f32

    (void)in_sizes; (void)n_in; (void)out_size;

    hash_ngram_kernel<<<BATCH * SEQ_LEN, 128>>>(tokens, main_w, shared_w, size_w, out);
}

// round 9
// speedup vs baseline: 1.0229x; 1.0081x over previous
#include <cuda_runtime.h>
#include <cuda_bf16.h>
#include <cstdint>

// Problem constants (match reference)
#define BATCH      4
#define SEQ_LEN    8192
#define EMBED_DIM  512
#define NBUCKETS   500000
#define HASH_MASK  0x7FFFFFu   // 2^23 - 1
#define HASH_BASE  260u        // VOCAB + 1
#define MAX_N      8

// One CTA per (b, s) position. 128 threads, each owns one float4 of the
// 512-dim embedding. Single launch: the 6 size_w rows (12KB, L1-resident
// after wave 1) are re-summed per thread into the running accumulator —
// this deletes the prologue kernel + graph gap (~1.9us) while keeping
// live state across the in-flight gathers to one float4.
__global__ __launch_bounds__(128, 10)
void hash_ngram_kernel(const int* __restrict__ tokens,
                       const float* __restrict__ main_w,
                       const float* __restrict__ shared_w,
                       const float* __restrict__ size_w,
                       float* __restrict__ out)
{
    const int pos = blockIdx.x;           // 0 .. BATCH*SEQ_LEN-1
    const int b   = pos >> 13;            // / SEQ_LEN
    const int s   = pos & (SEQ_LEN - 1);  // % SEQ_LEN

    __shared__ int tok[MAX_N];            // t[s], t[s-1], ..., t[s-7]

    if (threadIdx.x < MAX_N) {
        const int j = threadIdx.x;
        tok[j] = (s - j >= 0) ? tokens[b * SEQ_LEN + (s - j)] : 0;
    }
    __syncthreads();

    // Every thread computes the 6 bucket indices redundantly (pure ALU,
    // ~30 int ops) — avoids a second barrier / single-thread serialization.
    int sidx[MAX_N - 2];
    {
        unsigned P   = 1u;   // 260^j mod 2^23
        unsigned acc = 0u;   // running sum of masked terms
        #pragma unroll
        for (int j = 0; j < MAX_N; ++j) {
            acc += ((unsigned)tok[j] * P) & HASH_MASK;   // t[s-j]*260^j mod 2^23
            P = (P * HASH_BASE) & HASH_MASK;
            const int n = j + 1;                          // n-gram length
            if (n >= 3) {
                const unsigned h = acc & HASH_MASK;       // sum mod 2^23
                sidx[n - 3] = (s >= n - 1) ? (int)(h % NBUCKETS) : 0;
            }
        }
    }

    const int d4 = threadIdx.x;  // float4 lane, 0..127 (512/4)
    const float4* __restrict__ g4 = (const float4*)shared_w;
    const float4* __restrict__ m4 = (const float4*)main_w;
    const float4* __restrict__ z4 = (const float4*)size_w;

    // Issue the 6 DRAM gathers first for maximum MLP.
    float4 vg[MAX_N - 2];
    #pragma unroll
    for (int r = 0; r < MAX_N - 2; ++r)
        vg[r] = __ldg(&g4[(size_t)sidx[r] * 128 + d4]);

    // While gathers are in flight: cached contributions, accumulated
    // immediately (single float4 of live state, no arrays).
    float4 vm = __ldg(&m4[(size_t)tok[0] * 128 + d4]);   // L2-resident
    float ax = vm.x, ay = vm.y, az = vm.z, aw = vm.w;
    #pragma unroll
    for (int r = 0; r < MAX_N - 2; ++r) {
        const float4 vz = __ldg(&z4[(size_t)r * 128 + d4]);  // L1-resident
        ax += vz.x; ay += vz.y; az += vz.z; aw += vz.w;
    }

    // Consume the gathers.
    #pragma unroll
    for (int r = 0; r < MAX_N - 2; ++r) {
        ax += vg[r].x;
        ay += vg[r].y;
        az += vg[r].z;
        aw += vg[r].w;
    }

    const float inv = 1.0f / 7.0f;   // 1 + (MAX_N - 2) contributors
    float4 o;
    o.x = ax * inv; o.y = ay * inv; o.z = az * inv; o.w = aw * inv;
    // Streaming store: don't let the 64MB output evict gather lines from L2.
    __stcs(&((float4*)out)[(size_t)pos * 128 + d4], o);
}

extern "C" void kernel_launch(void* const* d_in, const int* in_sizes, int n_in,
                              void* d_out, int out_size)
{
    const int*   tokens   = (const int*)  d_in[0];   // [4, 8192] int32
    const float* main_w   = (const float*)d_in[1];   // [259, 512] f32
    const float* shared_w = (const float*)d_in[2];   // [500000, 512] f32
    const float* size_w   = (const float*)d_in[3];   // [6, 512] f32
    float*       out      = (float*)d_out;           // [4, 8192, 512] f32

    (void)in_sizes; (void)n_in; (void)out_size;

    hash_ngram_kernel<<<BATCH * SEQ_LEN, 128>>>(tokens, main_w, shared_w, size_w, out);
}

// round 10
// speedup vs baseline: 1.0383x; 1.0151x over previous
#include <cuda_runtime.h>
#include <cuda_bf16.h>
#include <cstdint>

// Problem constants (match reference)
#define BATCH      4
#define SEQ_LEN    8192
#define EMBED_DIM  512
#define NBUCKETS   500000
#define HASH_MASK  0x7FFFFFu   // 2^23 - 1
#define HASH_BASE  260u        // VOCAB + 1
#define MAX_N      8

// One CTA per (b, s) position; 128 threads, one float4 lane each.
// Single launch (no prologue: ~1us saved). __launch_bounds__(128,12) gives
// ptxas a hard 42-reg budget so the six L1-resident size_w loads cannot be
// batched into the gather LDG cluster (that batching is what pushed R5/R7
// to 48 regs and ~54% occupancy).
__global__ __launch_bounds__(128, 12)
void hash_ngram_kernel(const int* __restrict__ tokens,
                       const float* __restrict__ main_w,
                       const float* __restrict__ shared_w,
                       const float* __restrict__ size_w,
                       float* __restrict__ out)
{
    const int pos = blockIdx.x;           // 0 .. BATCH*SEQ_LEN-1
    const int b   = pos >> 13;            // / SEQ_LEN
    const int s   = pos & (SEQ_LEN - 1);  // % SEQ_LEN

    __shared__ int tok[MAX_N];            // t[s], t[s-1], ..., t[s-7]

    if (threadIdx.x < MAX_N) {
        const int j = threadIdx.x;
        tok[j] = (s - j >= 0) ? tokens[b * SEQ_LEN + (s - j)] : 0;
    }
    __syncthreads();

    // Every thread computes the 6 bucket indices redundantly (pure ALU,
    // ~30 int ops) — avoids a second barrier / single-thread serialization.
    int sidx[MAX_N - 2];
    {
        unsigned P   = 1u;   // 260^j mod 2^23
        unsigned acc = 0u;   // running sum of masked terms
        #pragma unroll
        for (int j = 0; j < MAX_N; ++j) {
            acc += ((unsigned)tok[j] * P) & HASH_MASK;   // t[s-j]*260^j mod 2^23
            P = (P * HASH_BASE) & HASH_MASK;
            const int n = j + 1;                          // n-gram length
            if (n >= 3) {
                const unsigned h = acc & HASH_MASK;       // sum mod 2^23
                sidx[n - 3] = (s >= n - 1) ? (int)(h % NBUCKETS) : 0;
            }
        }
    }

    const int d4 = threadIdx.x;  // float4 lane, 0..127 (512/4)
    const float4* __restrict__ g4 = (const float4*)shared_w;
    const float4* __restrict__ m4 = (const float4*)main_w;
    const float4* __restrict__ z4 = (const float4*)size_w;

    // Cached contributions FIRST (main_w row: L2-resident; size_w: 12KB,
    // L1-resident after wave 1). Accumulated immediately — their registers
    // are dead before the gathers need headroom.
    float4 vm = __ldg(&m4[(size_t)tok[0] * 128 + d4]);
    float ax = vm.x, ay = vm.y, az = vm.z, aw = vm.w;
    #pragma unroll
    for (int r = 0; r < MAX_N - 2; ++r) {
        const float4 vz = __ldg(&z4[(size_t)r * 128 + d4]);
        ax += vz.x; ay += vz.y; az += vz.z; aw += vz.w;
    }

    // The 6 DRAM gathers, batched for MLP.
    float4 vg[MAX_N - 2];
    #pragma unroll
    for (int r = 0; r < MAX_N - 2; ++r)
        vg[r] = __ldg(&g4[(size_t)sidx[r] * 128 + d4]);

    #pragma unroll
    for (int r = 0; r < MAX_N - 2; ++r) {
        ax += vg[r].x;
        ay += vg[r].y;
        az += vg[r].z;
        aw += vg[r].w;
    }

    const float inv = 1.0f / 7.0f;   // 1 + (MAX_N - 2) contributors
    float4 o;
    o.x = ax * inv; o.y = ay * inv; o.z = az * inv; o.w = aw * inv;
    // Streaming store: don't let the 64MB output evict gather lines from L2.
    __stcs(&((float4*)out)[(size_t)pos * 128 + d4], o);
}

extern "C" void kernel_launch(void* const* d_in, const int* in_sizes, int n_in,
                              void* d_out, int out_size)
{
    const int*   tokens   = (const int*)  d_in[0];   // [4, 8192] int32
    const float* main_w   = (const float*)d_in[1];   // [259, 512] f32
    const float* shared_w = (const float*)d_in[2];   // [500000, 512] f32
    const float* size_w   = (const float*)d_in[3];   // [6, 512] f32
    float*       out      = (float*)d_out;           // [4, 8192, 512] f32

    (void)in_sizes; (void)n_in; (void)out_size;

    hash_ngram_kernel<<<BATCH * SEQ_LEN, 128>>>(tokens, main_w, shared_w, size_w, out);
}